// round 3
// baseline (speedup 1.0000x reference)
#include <cuda_runtime.h>

#define N 8192
#define RANK 4
#define SCALING 2.0f   // ALPHA / RANK = 8 / 4
#define EPS 1e-5f
#define TPB 1024
#define GRID 296       // 2 CTAs/SM x 148 SMs, persistent
#define SMEM_BYTES (2 * N * (int)sizeof(float))

extern __shared__ float s_vec[];   // [0..N): scale, [N..2N): shift

__global__ __launch_bounds__(TPB, 2)
void lora_ln_persistent(const float* __restrict__ x,
                        const float* __restrict__ sA,
                        const float* __restrict__ sB,
                        const float* __restrict__ hA,
                        const float* __restrict__ hB,
                        float* __restrict__ out,
                        int rows) {
    float* __restrict__ s_scale = s_vec;
    float* __restrict__ s_shift = s_vec + N;
    __shared__ float s_sum[32], s_sq[32];
    __shared__ float s_mean, s_rstd;

    const int t = threadIdx.x;
    const int lane = t & 31, warp = t >> 5;

    // ---- Prologue: rank-4 low-rank diag -> per-feature scale/shift in smem.
    // 8 features per thread; A rows are float4, B rows coalesced across threads.
#pragma unroll
    for (int k = 0; k < N / TPB; k++) {
        const int i = t + k * TPB;
        float4 as = *(const float4*)(sA + i * RANK);
        float4 ah = *(const float4*)(hA + i * RANK);
        float sc = as.x * sB[0 * N + i] + as.y * sB[1 * N + i]
                 + as.z * sB[2 * N + i] + as.w * sB[3 * N + i];
        float sh = ah.x * hB[0 * N + i] + ah.y * hB[1 * N + i]
                 + ah.z * hB[2 * N + i] + ah.w * hB[3 * N + i];
        s_scale[i] = sc * SCALING;
        s_shift[i] = sh * SCALING;
    }
    __syncthreads();

    // Smem copies of the affine vectors for this thread's two float4 slots.
    const float4 sc0 = ((const float4*)s_scale)[t];
    const float4 sc1 = ((const float4*)s_scale)[t + TPB];
    const float4 sh0 = ((const float4*)s_shift)[t];
    const float4 sh1 = ((const float4*)s_shift)[t + TPB];

    // ---- Persistent row loop: each CTA handles rows blockIdx.x, +GRID, ...
    for (int row = blockIdx.x; row < rows; row += GRID) {
        const float4* __restrict__ xr = (const float4*)(x + (size_t)row * N);
        float4* __restrict__ yr = (float4*)(out + (size_t)row * N);

        // Streaming loads: x is read exactly once, keep it out of L2's way.
        float4 v0 = __ldcs(xr + t);
        float4 v1 = __ldcs(xr + t + TPB);

        float sum = v0.x + v0.y + v0.z + v0.w + v1.x + v1.y + v1.z + v1.w;
        float sq  = v0.x * v0.x + v0.y * v0.y + v0.z * v0.z + v0.w * v0.w
                  + v1.x * v1.x + v1.y * v1.y + v1.z * v1.z + v1.w * v1.w;

#pragma unroll
        for (int off = 16; off > 0; off >>= 1) {
            sum += __shfl_xor_sync(0xFFFFFFFFu, sum, off);
            sq  += __shfl_xor_sync(0xFFFFFFFFu, sq,  off);
        }
        if (lane == 0) { s_sum[warp] = sum; s_sq[warp] = sq; }
        __syncthreads();
        if (warp == 0) {
            float a = s_sum[lane], b = s_sq[lane];
#pragma unroll
            for (int off = 16; off > 0; off >>= 1) {
                a += __shfl_xor_sync(0xFFFFFFFFu, a, off);
                b += __shfl_xor_sync(0xFFFFFFFFu, b, off);
            }
            if (lane == 0) {
                float mean = a * (1.0f / N);
                float var  = b * (1.0f / N) - mean * mean;
                s_mean = mean;
                s_rstd = rsqrtf(var + EPS);
            }
        }
        __syncthreads();
        const float mean = s_mean, rstd = s_rstd;

        float4 o;
        o.x = (v0.x - mean) * rstd * sc0.x + sh0.x;
        o.y = (v0.y - mean) * rstd * sc0.y + sh0.y;
        o.z = (v0.z - mean) * rstd * sc0.z + sh0.z;
        o.w = (v0.w - mean) * rstd * sc0.w + sh0.w;
        __stcs(yr + t, o);
        o.x = (v1.x - mean) * rstd * sc1.x + sh1.x;
        o.y = (v1.y - mean) * rstd * sc1.y + sh1.y;
        o.z = (v1.z - mean) * rstd * sc1.z + sh1.z;
        o.w = (v1.w - mean) * rstd * sc1.w + sh1.w;
        __stcs(yr + t + TPB, o);
    }
}

extern "C" void kernel_launch(void* const* d_in, const int* in_sizes, int n_in,
                              void* d_out, int out_size) {
    const float* x  = (const float*)d_in[0];
    const float* sA = (const float*)d_in[1];
    const float* sB = (const float*)d_in[2];
    const float* hA = (const float*)d_in[3];
    const float* hB = (const float*)d_in[4];
    float* out = (float*)d_out;

    const int rows = out_size / N;   // 8192

    cudaFuncSetAttribute(lora_ln_persistent,
                         cudaFuncAttributeMaxDynamicSharedMemorySize, SMEM_BYTES);
    lora_ln_persistent<<<GRID, TPB, SMEM_BYTES>>>(x, sA, sB, hA, hB, out, rows);
}

// round 5
// speedup vs baseline: 1.1517x; 1.1517x over previous
#include <cuda_runtime.h>

#define N 8192
#define RANK 4
#define SCALING 2.0f   // ALPHA / RANK = 8 / 4
#define EPS 1e-5f
#define TPB 1024

// Allocation-free scratch for the adapted affine vectors.
__device__ float g_scale[N];
__device__ float g_shift[N];

// ---------------------------------------------------------------------------
// Kernel 1: rank-4 low-rank diagonal -> per-feature scale/shift vectors.
// ---------------------------------------------------------------------------
__global__ void lora_vectors_kernel(const float* __restrict__ sA,
                                    const float* __restrict__ sB,
                                    const float* __restrict__ hA,
                                    const float* __restrict__ hB) {
    int i = blockIdx.x * blockDim.x + threadIdx.x;
    if (i >= N) return;
    float4 a_s = *(const float4*)(sA + i * RANK);
    float4 a_h = *(const float4*)(hA + i * RANK);
    float s = a_s.x * sB[0 * N + i] + a_s.y * sB[1 * N + i]
            + a_s.z * sB[2 * N + i] + a_s.w * sB[3 * N + i];
    float h = a_h.x * hB[0 * N + i] + a_h.y * hB[1 * N + i]
            + a_h.z * hB[2 * N + i] + a_h.w * hB[3 * N + i];
    g_scale[i] = s * SCALING;
    g_shift[i] = h * SCALING;
}

// ---------------------------------------------------------------------------
// Kernel 2: fused LayerNorm, one CTA per row (R2 structure) with:
//  - scale/shift prefetched BEFORE the reduction (off the post-barrier path)
//  - single-barrier reduction (every warp redundantly folds the 32 partials)
// ---------------------------------------------------------------------------
__global__ __launch_bounds__(TPB) void lora_ln_kernel(const float* __restrict__ x,
                                                      float* __restrict__ out) {
    const int t = threadIdx.x;
    const int lane = t & 31, warp = t >> 5;
    const size_t row_off = (size_t)blockIdx.x * N;
    const float4* __restrict__ xr = (const float4*)(x + row_off);
    float4* __restrict__ yr = (float4*)(out + row_off);

    // Front-batched x loads (coalesced 128B).
    float4 v0 = xr[t];
    float4 v1 = xr[t + TPB];

    // Prefetch affine vectors NOW — independent of the reduction, so their
    // L2 latency overlaps the barrier wait instead of following it.
    const float4* __restrict__ sc = (const float4*)g_scale;
    const float4* __restrict__ sh = (const float4*)g_shift;
    float4 sc0 = sc[t];
    float4 sc1 = sc[t + TPB];
    float4 sh0 = sh[t];
    float4 sh1 = sh[t + TPB];

    float sum = v0.x + v0.y + v0.z + v0.w + v1.x + v1.y + v1.z + v1.w;
    float sq  = v0.x * v0.x + v0.y * v0.y + v0.z * v0.z + v0.w * v0.w
              + v1.x * v1.x + v1.y * v1.y + v1.z * v1.z + v1.w * v1.w;

#pragma unroll
    for (int off = 16; off > 0; off >>= 1) {
        sum += __shfl_xor_sync(0xFFFFFFFFu, sum, off);
        sq  += __shfl_xor_sync(0xFFFFFFFFu, sq,  off);
    }

    // Single barrier: lane0 of each warp publishes partials; afterwards every
    // warp redundantly reduces all 32 partials (no second __syncthreads).
    __shared__ float2 s_part[32];
    if (lane == 0) s_part[warp] = make_float2(sum, sq);
    __syncthreads();

    float2 p = s_part[lane];
#pragma unroll
    for (int off = 16; off > 0; off >>= 1) {
        p.x += __shfl_xor_sync(0xFFFFFFFFu, p.x, off);
        p.y += __shfl_xor_sync(0xFFFFFFFFu, p.y, off);
    }
    const float mean = p.x * (1.0f / N);
    const float var  = p.y * (1.0f / N) - mean * mean;
    const float rstd = rsqrtf(var + EPS);

    float4 o;
    o.x = (v0.x - mean) * rstd * sc0.x + sh0.x;
    o.y = (v0.y - mean) * rstd * sc0.y + sh0.y;
    o.z = (v0.z - mean) * rstd * sc0.z + sh0.z;
    o.w = (v0.w - mean) * rstd * sc0.w + sh0.w;
    yr[t] = o;
    o.x = (v1.x - mean) * rstd * sc1.x + sh1.x;
    o.y = (v1.y - mean) * rstd * sc1.y + sh1.y;
    o.z = (v1.z - mean) * rstd * sc1.z + sh1.z;
    o.w = (v1.w - mean) * rstd * sc1.w + sh1.w;
    yr[t + TPB] = o;
}

extern "C" void kernel_launch(void* const* d_in, const int* in_sizes, int n_in,
                              void* d_out, int out_size) {
    const float* x  = (const float*)d_in[0];
    const float* sA = (const float*)d_in[1];
    const float* sB = (const float*)d_in[2];
    const float* hA = (const float*)d_in[3];
    const float* hB = (const float*)d_in[4];
    float* out = (float*)d_out;

    const int rows = out_size / N;   // 8192

    lora_vectors_kernel<<<N / 256, 256>>>(sA, sB, hA, hB);
    lora_ln_kernel<<<rows, TPB>>>(x, out);
}

// round 8
// speedup vs baseline: 1.1586x; 1.0060x over previous
#include <cuda_runtime.h>

#define N 8192
#define RANK 4
#define SCALING 2.0f   // ALPHA / RANK = 8 / 4
#define EPS 1e-5f
#define TPB 1024

// Allocation-free scratch for the adapted affine vectors.
__device__ float g_scale[N];
__device__ float g_shift[N];

// ---------------------------------------------------------------------------
// Kernel 1: rank-4 low-rank diagonal -> per-feature scale/shift vectors.
// Triggers programmatic launch completion at entry so the LN kernel's CTAs
// can start their DRAM loads while this kernel runs.
// ---------------------------------------------------------------------------
__global__ void lora_vectors_kernel(const float* __restrict__ sA,
                                    const float* __restrict__ sB,
                                    const float* __restrict__ hA,
                                    const float* __restrict__ hB) {
    cudaTriggerProgrammaticLaunchCompletion();
    int i = blockIdx.x * blockDim.x + threadIdx.x;
    if (i >= N) return;
    float4 a_s = *(const float4*)(sA + i * RANK);
    float4 a_h = *(const float4*)(hA + i * RANK);
    float s = a_s.x * sB[0 * N + i] + a_s.y * sB[1 * N + i]
            + a_s.z * sB[2 * N + i] + a_s.w * sB[3 * N + i];
    float h = a_h.x * hB[0 * N + i] + a_h.y * hB[1 * N + i]
            + a_h.z * hB[2 * N + i] + a_h.w * hB[3 * N + i];
    g_scale[i] = s * SCALING;
    g_shift[i] = h * SCALING;
}

// ---------------------------------------------------------------------------
// Kernel 2: fused LayerNorm, one CTA per row (R3 structure), launched with
// PDL. x loads are issued first (independent of kernel 1), then we grid-sync
// on kernel 1's completion before reading the adapted affine vectors.
// ---------------------------------------------------------------------------
__global__ __launch_bounds__(TPB) void lora_ln_kernel(const float* __restrict__ x,
                                                      float* __restrict__ out) {
    const int t = threadIdx.x;
    const int lane = t & 31, warp = t >> 5;
    const size_t row_off = (size_t)blockIdx.x * N;
    const float4* __restrict__ xr = (const float4*)(x + row_off);
    float4* __restrict__ yr = (float4*)(out + row_off);

    // Front-batched x loads (coalesced 128B) — no dependence on kernel 1.
    float4 v0 = xr[t];
    float4 v1 = xr[t + TPB];

    // Wait for the vectors kernel; its runtime hides behind the x loads above.
    cudaGridDependencySynchronize();

    // Affine vectors (L1/L2-resident after first CTAs) — still hoisted ahead
    // of the reduction barrier so their latency overlaps the barrier wait.
    const float4* __restrict__ sc = (const float4*)g_scale;
    const float4* __restrict__ sh = (const float4*)g_shift;
    float4 sc0 = sc[t];
    float4 sc1 = sc[t + TPB];
    float4 sh0 = sh[t];
    float4 sh1 = sh[t + TPB];

    float sum = v0.x + v0.y + v0.z + v0.w + v1.x + v1.y + v1.z + v1.w;
    float sq  = v0.x * v0.x + v0.y * v0.y + v0.z * v0.z + v0.w * v0.w
              + v1.x * v1.x + v1.y * v1.y + v1.z * v1.z + v1.w * v1.w;

#pragma unroll
    for (int off = 16; off > 0; off >>= 1) {
        sum += __shfl_xor_sync(0xFFFFFFFFu, sum, off);
        sq  += __shfl_xor_sync(0xFFFFFFFFu, sq,  off);
    }

    // Single barrier: each warp publishes its partials, then every warp
    // redundantly folds all 32 (no second __syncthreads).
    __shared__ float2 s_part[32];
    if (lane == 0) s_part[warp] = make_float2(sum, sq);
    __syncthreads();

    float2 p = s_part[lane];
#pragma unroll
    for (int off = 16; off > 0; off >>= 1) {
        p.x += __shfl_xor_sync(0xFFFFFFFFu, p.x, off);
        p.y += __shfl_xor_sync(0xFFFFFFFFu, p.y, off);
    }
    const float mean = p.x * (1.0f / N);
    const float var  = p.y * (1.0f / N) - mean * mean;
    const float rstd = rsqrtf(var + EPS);

    float4 o;
    o.x = (v0.x - mean) * rstd * sc0.x + sh0.x;
    o.y = (v0.y - mean) * rstd * sc0.y + sh0.y;
    o.z = (v0.z - mean) * rstd * sc0.z + sh0.z;
    o.w = (v0.w - mean) * rstd * sc0.w + sh0.w;
    yr[t] = o;
    o.x = (v1.x - mean) * rstd * sc1.x + sh1.x;
    o.y = (v1.y - mean) * rstd * sc1.y + sh1.y;
    o.z = (v1.z - mean) * rstd * sc1.z + sh1.z;
    o.w = (v1.w - mean) * rstd * sc1.w + sh1.w;
    yr[t + TPB] = o;
}

extern "C" void kernel_launch(void* const* d_in, const int* in_sizes, int n_in,
                              void* d_out, int out_size) {
    const float* x  = (const float*)d_in[0];
    const float* sA = (const float*)d_in[1];
    const float* sB = (const float*)d_in[2];
    const float* hA = (const float*)d_in[3];
    const float* hB = (const float*)d_in[4];
    float* out = (float*)d_out;

    const int rows = out_size / N;   // 8192

    lora_vectors_kernel<<<N / 256, 256>>>(sA, sB, hA, hB);

    // LN kernel with programmatic dependent launch: starts while kernel 1
    // runs; device-side cudaGridDependencySynchronize() enforces the data
    // dependency on g_scale/g_shift.
    cudaLaunchConfig_t cfg = {};
    cfg.gridDim = dim3(rows, 1, 1);
    cfg.blockDim = dim3(TPB, 1, 1);
    cfg.dynamicSmemBytes = 0;
    cfg.stream = 0;
    cudaLaunchAttribute attrs[1];
    attrs[0].id = cudaLaunchAttributeProgrammaticStreamSerialization;
    attrs[0].val.programmaticStreamSerializationAllowed = 1;
    cfg.attrs = attrs;
    cfg.numAttrs = 1;
    cudaLaunchKernelEx(&cfg, lora_ln_kernel, x, out);
}